// round 9
// baseline (speedup 1.0000x reference)
#include <cuda_runtime.h>

#define NT   256
#define TT   512
#define ROWP 68

#define FMA2(d,a,b,c)  asm("fma.rn.f32x2 %0, %1, %2, %3;" : "=l"(d) : "l"(a), "l"(b), "l"(c))
#define SPLAT(d,s)     asm("mov.b64 %0, {%1, %1};" : "=l"(d) : "f"(s))
#define PACK2(d,lo,hi) asm("mov.b64 %0, {%1, %2};" : "=l"(d) : "f"(lo), "f"(hi))

union F2U { float2 f; unsigned long long u; };

__global__ __launch_bounds__(NT, 1)
void ttt_kernel(const float* __restrict__ XQ, const float* __restrict__ XK,
                const float* __restrict__ XV, const float* __restrict__ W1,
                const float* __restrict__ b1, const float* __restrict__ gam,
                const float* __restrict__ bet, float* __restrict__ out)
{
    __shared__ float W[4096];            // carried weights V_t
    __shared__ float xq_s[2][16*ROWP];   // tile double buffers
    __shared__ float xk_s[2][16*ROWP];
    __shared__ float gz_s[16*ROWP];
    __shared__ float x15_s[2][64];       // xk[15] row of step t, per parity
    __shared__ float bb[64];             // carried bias b_t
    __shared__ float eta_s[2][16];

    const int tid = threadIdx.x;
    const int bh  = blockIdx.x;
    const int hh  = bh & 15;
    const int k   = tid >> 4;            // token row 0..15
    const int q   = tid & 15;
    const int f0  = q << 2;              // 4 features per thread

    const size_t base = (size_t)bh * (TT * 1024);
    const float* xqg = XQ + base;
    const float* xkg = XK + base;
    const float* xvg = XV + base;
    float*       og  = out + base;

    // ---- init carried state ----
    {
        const float* Wg = W1 + (size_t)hh * 4096;
        #pragma unroll
        for (int i = 0; i < 4; i++)
            *(float4*)&W[i*1024 + tid*4] = *(const float4*)&Wg[i*1024 + tid*4];
        if (tid < 16)
            *(float4*)&bb[tid*4] = *(const float4*)&b1[hh*64 + tid*4];
    }
    const float4 g4  = *(const float4*)&gam[hh*64 + f0];
    const float4 be4 = *(const float4*)&bet[hh*64 + f0];

    // ---- stage tiles for steps 0 and 1; eta0, eta1 ----
    float4 cq = *(const float4*)&xqg[tid*4];            // step t registers
    float4 ck = *(const float4*)&xkg[tid*4];
    float4 cv = *(const float4*)&xvg[tid*4];
    float4 nq = *(const float4*)&xqg[1024 + tid*4];     // step t+1 registers
    float4 nk = *(const float4*)&xkg[1024 + tid*4];
    float4 nv = *(const float4*)&xvg[1024 + tid*4];
    *(float4*)&xq_s[0][k*ROWP + f0] = cq;
    *(float4*)&xk_s[0][k*ROWP + f0] = ck;
    *(float4*)&xq_s[1][k*ROWP + f0] = nq;
    *(float4*)&xk_s[1][k*ROWP + f0] = nk;
    {
        float s0 = ck.x*ck.x + ck.y*ck.y + ck.z*ck.z + ck.w*ck.w;
        float s1 = nk.x*nk.x + nk.y*nk.y + nk.z*nk.z + nk.w*nk.w;
        #pragma unroll
        for (int m = 8; m >= 1; m >>= 1) {
            s0 += __shfl_xor_sync(~0u, s0, m, 16);
            s1 += __shfl_xor_sync(~0u, s1, m, 16);
        }
        if (q == 0) {
            eta_s[0][k] = 0.01f / (1.0f + fmaxf(sqrtf(s0), 1e-6f));
            eta_s[1][k] = 0.01f / (1.0f + fmaxf(sqrtf(s1), 1e-6f));
        }
    }
    __syncthreads();

    // ---- prologue matmul for step 0 (against V_0, b_0) ----
    float4 zc  = *(const float4*)&bb[f0];
    float4 zdp = zc;
    float  a_cur = 1.0f;
    #pragma unroll 4
    for (int j = 0; j < 16; j++) {
        const int d0 = j << 2;
        const float4 xk4 = *(const float4*)&xk_s[0][k*ROWP + d0];
        const float4 xq4 = *(const float4*)&xq_s[0][k*ROWP + d0];
        const float4 xkA = *(const float4*)&xk_s[0][q*ROWP + d0];
        a_cur = fmaf(xq4.x, xkA.x, a_cur);
        a_cur = fmaf(xq4.y, xkA.y, a_cur);
        a_cur = fmaf(xq4.z, xkA.z, a_cur);
        a_cur = fmaf(xq4.w, xkA.w, a_cur);
        #pragma unroll
        for (int i = 0; i < 4; i++) {
            const float xkd = (&xk4.x)[i];
            const float xqd = (&xq4.x)[i];
            const float4 w = *(const float4*)&W[(d0+i)*64 + f0];
            zc.x  = fmaf(xkd, w.x, zc.x);   zc.y  = fmaf(xkd, w.y, zc.y);
            zc.z  = fmaf(xkd, w.z, zc.z);   zc.w  = fmaf(xkd, w.w, zc.w);
            zdp.x = fmaf(xqd, w.x, zdp.x);  zdp.y = fmaf(xqd, w.y, zdp.y);
            zdp.z = fmaf(xqd, w.z, zdp.z);  zdp.w = fmaf(xqd, w.w, zdp.w);
        }
    }

    for (int t = 0; t < TT; t++) {
        // ================= phase A: LN(z_t) -> gz, save xk15 ==============
        float em, el;
        {
            const float4 e0 = *(const float4*)&eta_s[t&1][0];
            const float4 e1 = *(const float4*)&eta_s[t&1][4];
            const float4 e2 = *(const float4*)&eta_s[t&1][8];
            const float4 e3 = *(const float4*)&eta_s[t&1][12];
            em = ((e0.x+e0.y+e0.z+e0.w) + (e1.x+e1.y+e1.z+e1.w)
                + (e2.x+e2.y+e2.z+e2.w) + (e3.x+e3.y+e3.z+e3.w)) * (1.0f/16.0f);
            el = e3.w;
        }
        {
            float s1 = zc.x + zc.y + zc.z + zc.w;
            float s2 = zc.x*zc.x + zc.y*zc.y + zc.z*zc.z + zc.w*zc.w;
            #pragma unroll
            for (int m = 8; m >= 1; m >>= 1) {
                s1 += __shfl_xor_sync(~0u, s1, m, 16);
                s2 += __shfl_xor_sync(~0u, s2, m, 16);
            }
            const float mu  = s1 * 0.015625f;
            const float var = fmaf(-mu, mu, s2 * 0.015625f);
            const float r   = rsqrtf(var + 1e-6f);
            float4 gz;
            gz.x = 2.0f * (fmaf(g4.x, (zc.x-mu)*r, be4.x) - cv.x + ck.x);
            gz.y = 2.0f * (fmaf(g4.y, (zc.y-mu)*r, be4.y) - cv.y + ck.y);
            gz.z = 2.0f * (fmaf(g4.z, (zc.z-mu)*r, be4.z) - cv.z + ck.z);
            gz.w = 2.0f * (fmaf(g4.w, (zc.w-mu)*r, be4.w) - cv.w + ck.w);
            *(float4*)&gz_s[k*ROWP + f0] = gz;
        }
        if (k == 15) *(float4*)&x15_s[t&1][f0] = ck;
        __syncthreads();                                          // S1

        // ================= phase B: big independent bundle ================
        const float4 gl = *(const float4*)&gz_s[15*ROWP + f0];
        const int more = (t + 1 < TT);

        // prefetch step t+2
        float4 pq = make_float4(0.f,0.f,0.f,0.f), pk = pq, pv = pq;
        if (t + 2 < TT) {
            const size_t off = (size_t)(t+2)*1024 + tid*4;
            pq = *(const float4*)&xqg[off];
            pk = *(const float4*)&xkg[off];
            pv = *(const float4*)&xvg[off];
        }

        // matmul for step t+1 against V_t, b_t (deferred-fix pipeline)
        F2U u01, u23, ud01, ud23, dkq;
        float a_nxt = 1.0f;
        u01.u = u23.u = ud01.u = ud23.u = dkq.u = 0ull;
        if (more) {
            const float* xqp  = &xq_s[(t+1)&1][0];
            const float* xkp  = &xk_s[(t+1)&1][0];
            const float* x15p = &x15_s[t&1][0];
            const ulonglong2 b2 = *(const ulonglong2*)&bb[f0];
            u01.u = b2.x; u23.u = b2.y; ud01.u = b2.x; ud23.u = b2.y;
            #pragma unroll 4
            for (int j = 0; j < 16; j++) {
                const int d0 = j << 2;
                const float4 xk4 = *(const float4*)&xkp[k*ROWP + d0];
                const float4 xq4 = *(const float4*)&xqp[k*ROWP + d0];
                const float4 xkA = *(const float4*)&xkp[q*ROWP + d0];
                const float4 x15 = *(const float4*)&x15p[d0];
                #pragma unroll
                for (int i = 0; i < 4; i++) {
                    const float xkd = (&xk4.x)[i];
                    const float xqd = (&xq4.x)[i];
                    const ulonglong2 w = *(const ulonglong2*)&W[(d0+i)*64 + f0];
                    unsigned long long sk, sq_, pkq, s15;
                    SPLAT(sk, xkd); SPLAT(sq_, xqd);
                    FMA2(u01.u,  sk,  w.x, u01.u);  FMA2(u23.u,  sk,  w.y, u23.u);
                    FMA2(ud01.u, sq_, w.x, ud01.u); FMA2(ud23.u, sq_, w.y, ud23.u);
                    PACK2(pkq, xkd, xqd); SPLAT(s15, (&x15.x)[i]);
                    FMA2(dkq.u, pkq, s15, dkq.u);
                    a_nxt = fmaf(xqd, (&xkA.x)[i], a_nxt);
                }
            }
        }

        // correction + LN2 + output for step t (overlaps matmul above)
        {
            F2U c01, c23; c01.u = 0ull; c23.u = 0ull;
            #pragma unroll
            for (int kp2 = 0; kp2 < 16; kp2++) {
                const float av = __shfl_sync(~0u, a_cur, kp2, 16);
                unsigned long long sav; SPLAT(sav, av);
                const ulonglong2 gv = *(const ulonglong2*)&gz_s[kp2*ROWP + f0];
                FMA2(c01.u, sav, gv.x, c01.u);
                FMA2(c23.u, sav, gv.y, c23.u);
            }
            float4 zd;
            zd.x = fmaf(-em, c01.f.x, zdp.x);
            zd.y = fmaf(-em, c01.f.y, zdp.y);
            zd.z = fmaf(-em, c23.f.x, zdp.z);
            zd.w = fmaf(-em, c23.f.y, zdp.w);
            float t1 = zd.x + zd.y + zd.z + zd.w;
            float t2 = zd.x*zd.x + zd.y*zd.y + zd.z*zd.z + zd.w*zd.w;
            #pragma unroll
            for (int m = 8; m >= 1; m >>= 1) {
                t1 += __shfl_xor_sync(~0u, t1, m, 16);
                t2 += __shfl_xor_sync(~0u, t2, m, 16);
            }
            const float mu2  = t1 * 0.015625f;
            const float var2 = fmaf(-mu2, mu2, t2 * 0.015625f);
            const float r2   = rsqrtf(var2 + 1e-6f);
            float4 o;
            o.x = cq.x + fmaf(g4.x, (zd.x-mu2)*r2, be4.x);
            o.y = cq.y + fmaf(g4.y, (zd.y-mu2)*r2, be4.y);
            o.z = cq.z + fmaf(g4.z, (zd.z-mu2)*r2, be4.z);
            o.w = cq.w + fmaf(g4.w, (zd.w-mu2)*r2, be4.w);
            *(float4*)&og[(size_t)t*1024 + tid*4] = o;
        }

        // stage step t+2 tiles + eta
        if (t + 2 < TT) {
            *(float4*)&xq_s[t&1][k*ROWP + f0] = pq;
            *(float4*)&xk_s[t&1][k*ROWP + f0] = pk;
            float ss = pk.x*pk.x + pk.y*pk.y + pk.z*pk.z + pk.w*pk.w;
            #pragma unroll
            for (int m = 8; m >= 1; m >>= 1) ss += __shfl_xor_sync(~0u, ss, m, 16);
            if (q == 0) eta_s[t&1][k] = 0.01f / (1.0f + fmaxf(sqrtf(ss), 1e-6f));
        }
        __syncthreads();                                          // S2

        // ========== phase C: W/b rank-1 update + deferred fix =============
        if (more) {
            #pragma unroll
            for (int j = 0; j < 4; j++) {
                const int d = k + 16*j;
                const float cf = -el * x15_s[t&1][d];
                float4 w4 = *(float4*)&W[d*64 + f0];
                w4.x = fmaf(cf, gl.x, w4.x); w4.y = fmaf(cf, gl.y, w4.y);
                w4.z = fmaf(cf, gl.z, w4.z); w4.w = fmaf(cf, gl.w, w4.w);
                *(float4*)&W[d*64 + f0] = w4;
            }
            if (tid < 16) {     // k==0, f0 == tid*4, gl == gz_s[15][f0]
                float4 bv = *(float4*)&bb[f0];
                bv.x = fmaf(-el, gl.x, bv.x); bv.y = fmaf(-el, gl.y, bv.y);
                bv.z = fmaf(-el, gl.z, bv.z); bv.w = fmaf(-el, gl.w, bv.w);
                *(float4*)&bb[f0] = bv;
            }
            // fix u -> z_{t+1}, ud -> zdp_{t+1}
            const float fk = -el * (dkq.f.x + 1.0f);
            const float fq = -el * (dkq.f.y + 1.0f);
            zc.x  = fmaf(fk, gl.x, u01.f.x);  zc.y  = fmaf(fk, gl.y, u01.f.y);
            zc.z  = fmaf(fk, gl.z, u23.f.x);  zc.w  = fmaf(fk, gl.w, u23.f.y);
            zdp.x = fmaf(fq, gl.x, ud01.f.x); zdp.y = fmaf(fq, gl.y, ud01.f.y);
            zdp.z = fmaf(fq, gl.z, ud23.f.x); zdp.w = fmaf(fq, gl.w, ud23.f.y);
            a_cur = a_nxt;
        }

        // rotate tile registers
        cq = nq; ck = nk; cv = nv;
        nq = pq; nk = pk; nv = pv;
    }
}

extern "C" void kernel_launch(void* const* d_in, const int* in_sizes, int n_in,
                              void* d_out, int out_size) {
    const float* XQ  = (const float*)d_in[0];
    const float* XK  = (const float*)d_in[1];
    const float* XV  = (const float*)d_in[2];
    const float* W1  = (const float*)d_in[3];
    const float* b1  = (const float*)d_in[4];
    const float* gam = (const float*)d_in[5];
    const float* bet = (const float*)d_in[6];
    float* out = (float*)d_out;

    const int nbh = in_sizes[0] / (TT * 16 * 64);   // B*H = 64
    ttt_kernel<<<nbh, NT>>>(XQ, XK, XV, W1, b1, gam, bet, out);
}

// round 10
// speedup vs baseline: 1.0233x; 1.0233x over previous
#include <cuda_runtime.h>

#define NT   256
#define TT   512
#define ROWP 68      // padded row stride (floats), multiple of 4 for LDS.128

#define CPA16(saddr, gptr) \
    asm volatile("cp.async.cg.shared.global [%0], [%1], 16;" :: "r"(saddr), "l"(gptr))
#define CPCOMMIT() asm volatile("cp.async.commit_group;")
#define CPWAIT0()  asm volatile("cp.async.wait_group 0;")

__global__ __launch_bounds__(NT, 1)
void ttt_kernel(const float* __restrict__ XQ, const float* __restrict__ XK,
                const float* __restrict__ XV, const float* __restrict__ W1,
                const float* __restrict__ b1, const float* __restrict__ gam,
                const float* __restrict__ bet, float* __restrict__ out)
{
    __shared__ float W[4096];            // W[d*64+f], carried
    __shared__ float xq_s[2][16*ROWP];   // double-buffered tiles
    __shared__ float xk_s[2][16*ROWP];
    __shared__ float xv_s[2][16*ROWP];
    __shared__ float gz_s[16*ROWP];
    __shared__ float bb[64];             // carried bias
    __shared__ float eta_s[2][16];

    const int tid = threadIdx.x;
    const int bh  = blockIdx.x;
    const int h   = bh & 15;
    const int k   = tid >> 4;            // token row 0..15
    const int q   = tid & 15;
    const int f0  = q << 2;              // 4 features per thread
    const int sl  = k*ROWP + f0;         // this thread's tile slot

    const size_t base = (size_t)bh * (TT * 1024);
    const float* xqg = XQ + base;
    const float* xkg = XK + base;
    const float* xvg = XV + base;
    float*       og  = out + base;

    // smem u32 addresses of this thread's slots (for cp.async)
    const unsigned sa_xq0 = (unsigned)__cvta_generic_to_shared(&xq_s[0][sl]);
    const unsigned sa_xq1 = (unsigned)__cvta_generic_to_shared(&xq_s[1][sl]);
    const unsigned sa_xk0 = (unsigned)__cvta_generic_to_shared(&xk_s[0][sl]);
    const unsigned sa_xk1 = (unsigned)__cvta_generic_to_shared(&xk_s[1][sl]);
    const unsigned sa_xv0 = (unsigned)__cvta_generic_to_shared(&xv_s[0][sl]);
    const unsigned sa_xv1 = (unsigned)__cvta_generic_to_shared(&xv_s[1][sl]);

    // ---- init carried state ----
    {
        const float* Wg = W1 + (size_t)h * 4096;
        #pragma unroll
        for (int i = 0; i < 4; i++)
            *(float4*)&W[i*1024 + tid*4] = *(const float4*)&Wg[i*1024 + tid*4];
        if (tid < 16)
            *(float4*)&bb[tid*4] = *(const float4*)&b1[h*64 + tid*4];
    }
    const float4 g4  = *(const float4*)&gam[h*64 + f0];
    const float4 be4 = *(const float4*)&bet[h*64 + f0];

    // ---- stage step-0 tiles directly + eta0 ----
    {
        const float4 q4 = *(const float4*)&xqg[tid*4];
        const float4 k4 = *(const float4*)&xkg[tid*4];
        const float4 v4 = *(const float4*)&xvg[tid*4];
        *(float4*)&xq_s[0][sl] = q4;
        *(float4*)&xk_s[0][sl] = k4;
        *(float4*)&xv_s[0][sl] = v4;
        float ss = k4.x*k4.x + k4.y*k4.y + k4.z*k4.z + k4.w*k4.w;
        #pragma unroll
        for (int m = 8; m >= 1; m >>= 1) ss += __shfl_xor_sync(~0u, ss, m, 16);
        if (q == 0) eta_s[0][k] = 0.01f / (1.0f + fmaxf(sqrtf(ss), 1e-6f));
    }
    __syncthreads();

    int p = 0;
    for (int t = 0; t < TT; t++) {
        // ---- issue async staging of step t+1 into the free buffer ----
        if (t + 1 < TT) {
            const size_t off = (size_t)(t+1)*1024 + tid*4;
            CPA16(p ? sa_xq0 : sa_xq1, xqg + off);
            CPA16(p ? sa_xk0 : sa_xk1, xkg + off);
            CPA16(p ? sa_xv0 : sa_xv1, xvg + off);
            CPCOMMIT();
        }

        // em = mean(eta), el = eta[15] (precomputed last step)
        float em, el;
        {
            const float4 e0 = *(const float4*)&eta_s[p][0];
            const float4 e1 = *(const float4*)&eta_s[p][4];
            const float4 e2 = *(const float4*)&eta_s[p][8];
            const float4 e3 = *(const float4*)&eta_s[p][12];
            em = ((e0.x+e0.y+e0.z+e0.w) + (e1.x+e1.y+e1.z+e1.w)
                + (e2.x+e2.y+e2.z+e2.w) + (e3.x+e3.y+e3.z+e3.w)) * (1.0f/16.0f);
            el = e3.w;
        }

        // ---- fused: z=xk@W+b, zd=xq@W+b, a=xq[k].xk[q]+1 ----
        const float* xqp = &xq_s[p][0];
        const float* xkp = &xk_s[p][0];
        float4 z  = *(const float4*)&bb[f0];
        float4 zd = z;
        float  a  = 1.0f;
        #pragma unroll 8
        for (int j = 0; j < 16; j++) {
            const int d0 = j << 2;
            const float4 xk4 = *(const float4*)&xkp[k*ROWP + d0];
            const float4 xq4 = *(const float4*)&xqp[k*ROWP + d0];
            const float4 xkA = *(const float4*)&xkp[q*ROWP + d0];
            a = fmaf(xq4.x, xkA.x, a);
            a = fmaf(xq4.y, xkA.y, a);
            a = fmaf(xq4.z, xkA.z, a);
            a = fmaf(xq4.w, xkA.w, a);
            {
                const float4 w = *(const float4*)&W[(d0+0)*64 + f0];
                z.x  = fmaf(xk4.x, w.x, z.x);  z.y  = fmaf(xk4.x, w.y, z.y);
                z.z  = fmaf(xk4.x, w.z, z.z);  z.w  = fmaf(xk4.x, w.w, z.w);
                zd.x = fmaf(xq4.x, w.x, zd.x); zd.y = fmaf(xq4.x, w.y, zd.y);
                zd.z = fmaf(xq4.x, w.z, zd.z); zd.w = fmaf(xq4.x, w.w, zd.w);
            }
            {
                const float4 w = *(const float4*)&W[(d0+1)*64 + f0];
                z.x  = fmaf(xk4.y, w.x, z.x);  z.y  = fmaf(xk4.y, w.y, z.y);
                z.z  = fmaf(xk4.y, w.z, z.z);  z.w  = fmaf(xk4.y, w.w, z.w);
                zd.x = fmaf(xq4.y, w.x, zd.x); zd.y = fmaf(xq4.y, w.y, zd.y);
                zd.z = fmaf(xq4.y, w.z, zd.z); zd.w = fmaf(xq4.y, w.w, zd.w);
            }
            {
                const float4 w = *(const float4*)&W[(d0+2)*64 + f0];
                z.x  = fmaf(xk4.z, w.x, z.x);  z.y  = fmaf(xk4.z, w.y, z.y);
                z.z  = fmaf(xk4.z, w.z, z.z);  z.w  = fmaf(xk4.z, w.w, z.w);
                zd.x = fmaf(xq4.z, w.x, zd.x); zd.y = fmaf(xq4.z, w.y, zd.y);
                zd.z = fmaf(xq4.z, w.z, zd.z); zd.w = fmaf(xq4.z, w.w, zd.w);
            }
            {
                const float4 w = *(const float4*)&W[(d0+3)*64 + f0];
                z.x  = fmaf(xk4.w, w.x, z.x);  z.y  = fmaf(xk4.w, w.y, z.y);
                z.z  = fmaf(xk4.w, w.z, z.z);  z.w  = fmaf(xk4.w, w.w, z.w);
                zd.x = fmaf(xq4.w, w.x, zd.x); zd.y = fmaf(xq4.w, w.y, zd.y);
                zd.z = fmaf(xq4.w, w.z, zd.z); zd.w = fmaf(xq4.w, w.w, zd.w);
            }
        }

        // ---- LN(z) single-pass -> grad_Z1 (ck/cv re-read from smem; their
        //      LDS latency hides under the shuffle chain) ----
        const float4 ck = *(const float4*)&xkp[sl];
        const float4 cv = *(const float4*)&xv_s[p][sl];
        float s1 = z.x + z.y + z.z + z.w;
        float s2 = z.x*z.x + z.y*z.y + z.z*z.z + z.w*z.w;
        #pragma unroll
        for (int m = 8; m >= 1; m >>= 1) {
            s1 += __shfl_xor_sync(~0u, s1, m, 16);
            s2 += __shfl_xor_sync(~0u, s2, m, 16);
        }
        const float mu  = s1 * 0.015625f;
        const float var = fmaf(-mu, mu, s2 * 0.015625f);
        const float r   = rsqrtf(var + 1e-6f);
        float4 gz;
        gz.x = 2.0f * (fmaf(g4.x, (z.x-mu)*r, be4.x) - cv.x + ck.x);
        gz.y = 2.0f * (fmaf(g4.y, (z.y-mu)*r, be4.y) - cv.y + ck.y);
        gz.z = 2.0f * (fmaf(g4.z, (z.z-mu)*r, be4.z) - cv.z + ck.z);
        gz.w = 2.0f * (fmaf(g4.w, (z.w-mu)*r, be4.w) - cv.w + ck.w);
        *(float4*)&gz_s[k*ROWP + f0] = gz;
        __syncthreads();                                   // S2

        // ---- carry update: rank-1, in place ----
        {
            const float4 gl = *(const float4*)&gz_s[15*ROWP + f0];
            #pragma unroll
            for (int j = 0; j < 4; j++) {
                const int d = k + 16*j;
                const float cf = -el * xkp[15*ROWP + d];
                float4 w4 = *(float4*)&W[d*64 + f0];
                w4.x = fmaf(cf, gl.x, w4.x); w4.y = fmaf(cf, gl.y, w4.y);
                w4.z = fmaf(cf, gl.z, w4.z); w4.w = fmaf(cf, gl.w, w4.w);
                *(float4*)&W[d*64 + f0] = w4;
            }
            if (tid < 16) {   // k==0, f0 == tid*4, gl == gz_s[15][f0]
                float4 bv = *(float4*)&bb[f0];
                bv.x = fmaf(-el, gl.x, bv.x); bv.y = fmaf(-el, gl.y, bv.y);
                bv.z = fmaf(-el, gl.z, bv.z); bv.w = fmaf(-el, gl.w, bv.w);
                *(float4*)&bb[f0] = bv;
            }
        }

        // ---- correction: zd -= em * (A' @ gz), A' via half-warp shfl ----
        float4 c = make_float4(0.f,0.f,0.f,0.f);
        #pragma unroll
        for (int kp2 = 0; kp2 < 16; kp2++) {
            const float av  = __shfl_sync(~0u, a, kp2, 16);
            const float4 gv = *(const float4*)&gz_s[kp2*ROWP + f0];
            c.x = fmaf(av, gv.x, c.x); c.y = fmaf(av, gv.y, c.y);
            c.z = fmaf(av, gv.z, c.z); c.w = fmaf(av, gv.w, c.w);
        }
        zd.x = fmaf(-em, c.x, zd.x); zd.y = fmaf(-em, c.y, zd.y);
        zd.z = fmaf(-em, c.z, zd.z); zd.w = fmaf(-em, c.w, zd.w);

        // ---- LN(zd) single-pass, out = xq + ln ----
        const float4 cq = *(const float4*)&xqp[sl];
        float t1 = zd.x + zd.y + zd.z + zd.w;
        float t2 = zd.x*zd.x + zd.y*zd.y + zd.z*zd.z + zd.w*zd.w;
        #pragma unroll
        for (int m = 8; m >= 1; m >>= 1) {
            t1 += __shfl_xor_sync(~0u, t1, m, 16);
            t2 += __shfl_xor_sync(~0u, t2, m, 16);
        }
        const float mu2  = t1 * 0.015625f;
        const float var2 = fmaf(-mu2, mu2, t2 * 0.015625f);
        const float r2   = rsqrtf(var2 + 1e-6f);
        float4 o;
        o.x = cq.x + fmaf(g4.x, (zd.x-mu2)*r2, be4.x);
        o.y = cq.y + fmaf(g4.y, (zd.y-mu2)*r2, be4.y);
        o.z = cq.z + fmaf(g4.z, (zd.z-mu2)*r2, be4.z);
        o.w = cq.w + fmaf(g4.w, (zd.w-mu2)*r2, be4.w);
        *(float4*)&og[(size_t)t*1024 + tid*4] = o;

        // ---- finish staging: compute eta_{t+1} from arrived tile ----
        if (t + 1 < TT) {
            CPWAIT0();
            const float4 nk = *(const float4*)&xk_s[p^1][sl];
            float ss = nk.x*nk.x + nk.y*nk.y + nk.z*nk.z + nk.w*nk.w;
            #pragma unroll
            for (int m = 8; m >= 1; m >>= 1) ss += __shfl_xor_sync(~0u, ss, m, 16);
            if (q == 0) eta_s[p^1][k] = 0.01f / (1.0f + fmaxf(sqrtf(ss), 1e-6f));
        }
        __syncthreads();                                   // S3

        p ^= 1;
    }
}

extern "C" void kernel_launch(void* const* d_in, const int* in_sizes, int n_in,
                              void* d_out, int out_size) {
    const float* XQ  = (const float*)d_in[0];
    const float* XK  = (const float*)d_in[1];
    const float* XV  = (const float*)d_in[2];
    const float* W1  = (const float*)d_in[3];
    const float* b1  = (const float*)d_in[4];
    const float* gam = (const float*)d_in[5];
    const float* bet = (const float*)d_in[6];
    float* out = (float*)d_out;

    const int nbh = in_sizes[0] / (TT * 16 * 64);   // B*H = 64
    ttt_kernel<<<nbh, NT>>>(XQ, XK, XV, W1, b1, gam, bet, out);
}

// round 11
// speedup vs baseline: 1.7468x; 1.7070x over previous
#include <cuda_runtime.h>

#define TT     512
#define CHUNK  16
#define NCHUNK 32
#define NBH    64
#define ROWP   68

__device__ float g_Wsnap[(size_t)NBH * NCHUNK * 4096];
__device__ float g_bsnap[(size_t)NBH * NCHUNK * 64];

// ================== kernel 1: sequential rank-1 scan (1 warp/chain) =========
__global__ __launch_bounds__(32, 1)
void scan_kernel(const float* __restrict__ XK, const float* __restrict__ XV,
                 const float* __restrict__ W1, const float* __restrict__ b1,
                 const float* __restrict__ gam, const float* __restrict__ bet)
{
    const int lane = threadIdx.x;
    const int bh   = blockIdx.x;
    const int h    = bh & 15;
    __shared__ float xs[64];

    float Wa[64], Wb[64];
    {
        const float* Wg = W1 + (size_t)h * 4096;
        #pragma unroll
        for (int d = 0; d < 64; d++) {
            Wa[d] = Wg[d*64 + lane];
            Wb[d] = Wg[d*64 + lane + 32];
        }
    }
    float bav = b1[h*64 + lane], bbv = b1[h*64 + lane + 32];
    const float ga  = gam[h*64 + lane], gb  = gam[h*64 + lane + 32];
    const float bea = bet[h*64 + lane], beb = bet[h*64 + lane + 32];

    const size_t base = (size_t)bh * (TT * 1024) + 960;   // row 15 of each step
    const float* xkg = XK + base;
    const float* xvg = XV + base;

    float ka = xkg[lane], kb = xkg[lane + 32];
    float va = xvg[lane], vb = xvg[lane + 32];

    for (int t = 0; t < TT; t++) {
        // ---- snapshot W,b at chunk boundary (before this step's update) ----
        if ((t & (CHUNK-1)) == 0) {
            const int c = t >> 4;
            float* ws = g_Wsnap + ((size_t)bh * NCHUNK + c) * 4096;
            #pragma unroll
            for (int d = 0; d < 64; d++) {
                ws[d*64 + lane]      = Wa[d];
                ws[d*64 + lane + 32] = Wb[d];
            }
            float* bs = g_bsnap + ((size_t)bh * NCHUNK + c) * 64;
            bs[lane] = bav; bs[lane + 32] = bbv;
        }

        // ---- prefetch next step's row-15 data ----
        float nka = 0.f, nkb = 0.f, nva = 0.f, nvb = 0.f;
        if (t + 1 < TT) {
            const size_t o = (size_t)(t+1) * 1024;
            nka = xkg[o + lane]; nkb = xkg[o + lane + 32];
            nva = xvg[o + lane]; nvb = xvg[o + lane + 32];
        }

        // ---- el = eta of last token ----
        float ss = ka*ka + kb*kb;
        #pragma unroll
        for (int m = 16; m >= 1; m >>= 1) ss += __shfl_xor_sync(~0u, ss, m);
        const float el = 0.01f / (1.0f + fmaxf(sqrtf(ss), 1e-6f));

        // ---- stage xk15 for broadcast ----
        xs[lane] = ka; xs[lane + 32] = kb;
        __syncwarp();

        // ---- z15 = xk15 @ W + b (4-way split chains) ----
        float z0=0.f,z1=0.f,z2=0.f,z3=0.f, y0=0.f,y1=0.f,y2=0.f,y3=0.f;
        #pragma unroll
        for (int d = 0; d < 64; d += 4) {
            const float x0 = xs[d], x1 = xs[d+1], x2 = xs[d+2], x3 = xs[d+3];
            z0 = fmaf(x0, Wa[d],   z0);  y0 = fmaf(x0, Wb[d],   y0);
            z1 = fmaf(x1, Wa[d+1], z1);  y1 = fmaf(x1, Wb[d+1], y1);
            z2 = fmaf(x2, Wa[d+2], z2);  y2 = fmaf(x2, Wb[d+2], y2);
            z3 = fmaf(x3, Wa[d+3], z3);  y3 = fmaf(x3, Wb[d+3], y3);
        }
        const float za = bav + ((z0 + z1) + (z2 + z3));
        const float zb = bbv + ((y0 + y1) + (y2 + y3));

        // ---- LN over 64 features -> gz15 ----
        float s1 = za + zb;
        float s2 = za*za + zb*zb;
        #pragma unroll
        for (int m = 16; m >= 1; m >>= 1) {
            s1 += __shfl_xor_sync(~0u, s1, m);
            s2 += __shfl_xor_sync(~0u, s2, m);
        }
        const float mu  = s1 * 0.015625f;
        const float var = fmaf(-mu, mu, s2 * 0.015625f);
        const float r   = rsqrtf(var + 1e-6f);
        const float gza = 2.0f * (fmaf(ga, (za-mu)*r, bea) - va + ka);
        const float gzb = 2.0f * (fmaf(gb, (zb-mu)*r, beb) - vb + kb);

        // ---- rank-1 update ----
        const float ea = el * gza, eb = el * gzb;
        #pragma unroll
        for (int d = 0; d < 64; d++) {
            const float x = xs[d];
            Wa[d] = fmaf(-ea, x, Wa[d]);
            Wb[d] = fmaf(-eb, x, Wb[d]);
        }
        bav = fmaf(-el, gza, bav);
        bbv = fmaf(-el, gzb, bbv);

        __syncwarp();
        ka = nka; kb = nkb; va = nva; vb = nvb;
    }
}

// ============ kernel 2: parallel chunk replay (R5 body, 16 steps) ===========
__global__ __launch_bounds__(256)
void chunk_kernel(const float* __restrict__ XQ, const float* __restrict__ XK,
                  const float* __restrict__ XV, const float* __restrict__ gam,
                  const float* __restrict__ bet, float* __restrict__ out)
{
    __shared__ float W[4096];
    __shared__ float xq_s[2][16*ROWP];
    __shared__ float xk_s[2][16*ROWP];
    __shared__ float gz_s[16*ROWP];
    __shared__ float bb[64];
    __shared__ float eta_s[2][16];

    const int tid = threadIdx.x;
    const int c   = blockIdx.x;           // chunk 0..31
    const int bh  = blockIdx.y;           // chain 0..63
    const int h   = bh & 15;
    const int k   = tid >> 4;
    const int q   = tid & 15;
    const int f0  = q << 2;

    const size_t base = (size_t)bh * (TT * 1024) + (size_t)c * (CHUNK * 1024);
    const float* xqg = XQ + base;
    const float* xkg = XK + base;
    const float* xvg = XV + base;
    float*       og  = out + base;

    // ---- init carried state from snapshot ----
    {
        const float* Ws = g_Wsnap + ((size_t)bh * NCHUNK + c) * 4096;
        #pragma unroll
        for (int i = 0; i < 4; i++)
            *(float4*)&W[i*1024 + tid*4] = *(const float4*)&Ws[i*1024 + tid*4];
        if (tid < 16) {
            const float* bs = g_bsnap + ((size_t)bh * NCHUNK + c) * 64;
            *(float4*)&bb[tid*4] = *(const float4*)&bs[tid*4];
        }
    }
    const float4 g4  = *(const float4*)&gam[h*64 + f0];
    const float4 be4 = *(const float4*)&bet[h*64 + f0];

    // ---- stage local step 0 ----
    float4 q4 = *(const float4*)&xqg[tid*4];
    float4 k4 = *(const float4*)&xkg[tid*4];
    float4 v4 = *(const float4*)&xvg[tid*4];
    *(float4*)&xq_s[0][k*ROWP + f0] = q4;
    *(float4*)&xk_s[0][k*ROWP + f0] = k4;
    {
        float ss = k4.x*k4.x + k4.y*k4.y + k4.z*k4.z + k4.w*k4.w;
        #pragma unroll
        for (int m = 8; m >= 1; m >>= 1) ss += __shfl_xor_sync(~0u, ss, m, 16);
        if (q == 0) eta_s[0][k] = 0.01f / (1.0f + fmaxf(sqrtf(ss), 1e-6f));
    }
    __syncthreads();

    int p = 0;
    for (int t = 0; t < CHUNK; t++) {
        // prefetch next local step
        float4 nq4 = make_float4(0.f,0.f,0.f,0.f), nk4 = nq4, nv4 = nq4;
        if (t + 1 < CHUNK) {
            const size_t off = (size_t)(t+1)*1024 + tid*4;
            nq4 = *(const float4*)&xqg[off];
            nk4 = *(const float4*)&xkg[off];
            nv4 = *(const float4*)&xvg[off];
        }

        float em, el;
        {
            const float4 e0 = *(const float4*)&eta_s[p][0];
            const float4 e1 = *(const float4*)&eta_s[p][4];
            const float4 e2 = *(const float4*)&eta_s[p][8];
            const float4 e3 = *(const float4*)&eta_s[p][12];
            em = ((e0.x+e0.y+e0.z+e0.w) + (e1.x+e1.y+e1.z+e1.w)
                + (e2.x+e2.y+e2.z+e2.w) + (e3.x+e3.y+e3.z+e3.w)) * (1.0f/16.0f);
            el = e3.w;
        }

        const float* xqp = &xq_s[p][0];
        const float* xkp = &xk_s[p][0];
        float4 z  = *(const float4*)&bb[f0];
        float4 zd = z;
        float  a  = 1.0f;
        #pragma unroll 4
        for (int j = 0; j < 16; j++) {
            const int d0 = j << 2;
            const float4 xk4 = *(const float4*)&xkp[k*ROWP + d0];
            const float4 xq4 = *(const float4*)&xqp[k*ROWP + d0];
            const float4 xkA = *(const float4*)&xkp[q*ROWP + d0];
            a = fmaf(xq4.x, xkA.x, a);
            a = fmaf(xq4.y, xkA.y, a);
            a = fmaf(xq4.z, xkA.z, a);
            a = fmaf(xq4.w, xkA.w, a);
            {
                const float4 w = *(const float4*)&W[(d0+0)*64 + f0];
                z.x  = fmaf(xk4.x, w.x, z.x);  z.y  = fmaf(xk4.x, w.y, z.y);
                z.z  = fmaf(xk4.x, w.z, z.z);  z.w  = fmaf(xk4.x, w.w, z.w);
                zd.x = fmaf(xq4.x, w.x, zd.x); zd.y = fmaf(xq4.x, w.y, zd.y);
                zd.z = fmaf(xq4.x, w.z, zd.z); zd.w = fmaf(xq4.x, w.w, zd.w);
            }
            {
                const float4 w = *(const float4*)&W[(d0+1)*64 + f0];
                z.x  = fmaf(xk4.y, w.x, z.x);  z.y  = fmaf(xk4.y, w.y, z.y);
                z.z  = fmaf(xk4.y, w.z, z.z);  z.w  = fmaf(xk4.y, w.w, z.w);
                zd.x = fmaf(xq4.y, w.x, zd.x); zd.y = fmaf(xq4.y, w.y, zd.y);
                zd.z = fmaf(xq4.y, w.z, zd.z); zd.w = fmaf(xq4.y, w.w, zd.w);
            }
            {
                const float4 w = *(const float4*)&W[(d0+2)*64 + f0];
                z.x  = fmaf(xk4.z, w.x, z.x);  z.y  = fmaf(xk4.z, w.y, z.y);
                z.z  = fmaf(xk4.z, w.z, z.z);  z.w  = fmaf(xk4.z, w.w, z.w);
                zd.x = fmaf(xq4.z, w.x, zd.x); zd.y = fmaf(xq4.z, w.y, zd.y);
                zd.z = fmaf(xq4.z, w.z, zd.z); zd.w = fmaf(xq4.z, w.w, zd.w);
            }
            {
                const float4 w = *(const float4*)&W[(d0+3)*64 + f0];
                z.x  = fmaf(xk4.w, w.x, z.x);  z.y  = fmaf(xk4.w, w.y, z.y);
                z.z  = fmaf(xk4.w, w.z, z.z);  z.w  = fmaf(xk4.w, w.w, z.w);
                zd.x = fmaf(xq4.w, w.x, zd.x); zd.y = fmaf(xq4.w, w.y, zd.y);
                zd.z = fmaf(xq4.w, w.z, zd.z); zd.w = fmaf(xq4.w, w.w, zd.w);
            }
        }

        // LN(z) -> gz
        float s1 = z.x + z.y + z.z + z.w;
        float s2 = z.x*z.x + z.y*z.y + z.z*z.z + z.w*z.w;
        #pragma unroll
        for (int m = 8; m >= 1; m >>= 1) {
            s1 += __shfl_xor_sync(~0u, s1, m, 16);
            s2 += __shfl_xor_sync(~0u, s2, m, 16);
        }
        const float mu  = s1 * 0.015625f;
        const float var = fmaf(-mu, mu, s2 * 0.015625f);
        const float r   = rsqrtf(var + 1e-6f);
        float4 gz;
        gz.x = 2.0f * (fmaf(g4.x, (z.x-mu)*r, be4.x) - v4.x + k4.x);
        gz.y = 2.0f * (fmaf(g4.y, (z.y-mu)*r, be4.y) - v4.y + k4.y);
        gz.z = 2.0f * (fmaf(g4.z, (z.z-mu)*r, be4.z) - v4.z + k4.z);
        gz.w = 2.0f * (fmaf(g4.w, (z.w-mu)*r, be4.w) - v4.w + k4.w);
        *(float4*)&gz_s[k*ROWP + f0] = gz;
        __syncthreads();

        // rank-1 carry update (skip on last local step: next chunk has its own snapshot)
        if (t + 1 < CHUNK) {
            const float4 gl = *(const float4*)&gz_s[15*ROWP + f0];
            #pragma unroll
            for (int j = 0; j < 4; j++) {
                const int d = k + 16*j;
                const float cf = -el * xkp[15*ROWP + d];
                float4 w4 = *(float4*)&W[d*64 + f0];
                w4.x = fmaf(cf, gl.x, w4.x); w4.y = fmaf(cf, gl.y, w4.y);
                w4.z = fmaf(cf, gl.z, w4.z); w4.w = fmaf(cf, gl.w, w4.w);
                *(float4*)&W[d*64 + f0] = w4;
            }
            if (tid < 16) {
                float4 bv = *(float4*)&bb[f0];
                bv.x = fmaf(-el, gl.x, bv.x); bv.y = fmaf(-el, gl.y, bv.y);
                bv.z = fmaf(-el, gl.z, bv.z); bv.w = fmaf(-el, gl.w, bv.w);
                *(float4*)&bb[f0] = bv;
            }
        }

        // correction: zd -= em * (A' @ gz)
        float4 cc = make_float4(0.f,0.f,0.f,0.f);
        #pragma unroll
        for (int kp2 = 0; kp2 < 16; kp2++) {
            const float av  = __shfl_sync(~0u, a, kp2, 16);
            const float4 gv = *(const float4*)&gz_s[kp2*ROWP + f0];
            cc.x = fmaf(av, gv.x, cc.x); cc.y = fmaf(av, gv.y, cc.y);
            cc.z = fmaf(av, gv.z, cc.z); cc.w = fmaf(av, gv.w, cc.w);
        }
        zd.x = fmaf(-em, cc.x, zd.x); zd.y = fmaf(-em, cc.y, zd.y);
        zd.z = fmaf(-em, cc.z, zd.z); zd.w = fmaf(-em, cc.w, zd.w);

        // LN(zd), out = xq + ln
        float t1 = zd.x + zd.y + zd.z + zd.w;
        float t2 = zd.x*zd.x + zd.y*zd.y + zd.z*zd.z + zd.w*zd.w;
        #pragma unroll
        for (int m = 8; m >= 1; m >>= 1) {
            t1 += __shfl_xor_sync(~0u, t1, m, 16);
            t2 += __shfl_xor_sync(~0u, t2, m, 16);
        }
        const float mu2  = t1 * 0.015625f;
        const float var2 = fmaf(-mu2, mu2, t2 * 0.015625f);
        const float r2   = rsqrtf(var2 + 1e-6f);
        float4 o;
        o.x = q4.x + fmaf(g4.x, (zd.x-mu2)*r2, be4.x);
        o.y = q4.y + fmaf(g4.y, (zd.y-mu2)*r2, be4.y);
        o.z = q4.z + fmaf(g4.z, (zd.z-mu2)*r2, be4.z);
        o.w = q4.w + fmaf(g4.w, (zd.w-mu2)*r2, be4.w);
        *(float4*)&og[(size_t)t*1024 + tid*4] = o;

        // stage next local step
        const int pn = p ^ 1;
        if (t + 1 < CHUNK) {
            *(float4*)&xq_s[pn][k*ROWP + f0] = nq4;
            *(float4*)&xk_s[pn][k*ROWP + f0] = nk4;
            float ss = nk4.x*nk4.x + nk4.y*nk4.y + nk4.z*nk4.z + nk4.w*nk4.w;
            #pragma unroll
            for (int m = 8; m >= 1; m >>= 1) ss += __shfl_xor_sync(~0u, ss, m, 16);
            if (q == 0) eta_s[pn][k] = 0.01f / (1.0f + fmaxf(sqrtf(ss), 1e-6f));
        }
        __syncthreads();

        q4 = nq4; k4 = nk4; v4 = nv4; p = pn;
    }
}

extern "C" void kernel_launch(void* const* d_in, const int* in_sizes, int n_in,
                              void* d_out, int out_size) {
    const float* XQ  = (const float*)d_in[0];
    const float* XK  = (const float*)d_in[1];
    const float* XV  = (const float*)d_in[2];
    const float* W1  = (const float*)d_in[3];
    const float* b1  = (const float*)d_in[4];
    const float* gam = (const float*)d_in[5];
    const float* bet = (const float*)d_in[6];
    float* out = (float*)d_out;

    const int nbh = in_sizes[0] / (TT * 16 * 64);   // B*H = 64
    scan_kernel<<<nbh, 32>>>(XK, XV, W1, b1, gam, bet);
    chunk_kernel<<<dim3(NCHUNK, nbh), 256>>>(XQ, XK, XV, gam, bet, out);
}

// round 12
// speedup vs baseline: 1.9696x; 1.1276x over previous
#include <cuda_runtime.h>

#define TT     512
#define CHUNK  16
#define NPAIR  8
#define NCHUNK 32
#define NBH    64
#define ROWP   68

__device__ float g_Wsnap[(size_t)NBH * NCHUNK * 4096];
__device__ float g_bsnap[(size_t)NBH * NCHUNK * 64];

#define CPA16(saddr, gptr) \
    asm volatile("cp.async.cg.shared.global [%0], [%1], 16;" :: "r"(saddr), "l"(gptr))
#define CPCOMMIT() asm volatile("cp.async.commit_group;")
#define CPWAIT0()  asm volatile("cp.async.wait_group 0;")

// ============ kernel 1: sequential rank-1 scan, 4-warp d-split ==============
__global__ __launch_bounds__(128, 1)
void scan_kernel(const float* __restrict__ XK, const float* __restrict__ XV,
                 const float* __restrict__ W1, const float* __restrict__ b1,
                 const float* __restrict__ gam, const float* __restrict__ bet)
{
    __shared__ float xs[64];
    __shared__ float pz[4][64];
    __shared__ float gs[64];

    const int tid  = threadIdx.x;
    const int lane = tid & 31;
    const int w    = tid >> 5;
    const int bh   = blockIdx.x;
    const int h    = bh & 15;

    // warp w owns W rows d = w*16 .. w*16+15; lane owns features (lane, lane+32)
    float Wa[16], Wb[16];
    {
        const float* Wg = W1 + (size_t)h * 4096;
        #pragma unroll
        for (int i = 0; i < 16; i++) {
            const int d = w*16 + i;
            Wa[i] = Wg[d*64 + lane];
            Wb[i] = Wg[d*64 + lane + 32];
        }
    }
    float bav = b1[h*64 + lane], bbv = b1[h*64 + lane + 32];
    const float ga  = gam[h*64 + lane], gb  = gam[h*64 + lane + 32];
    const float bea = bet[h*64 + lane], beb = bet[h*64 + lane + 32];

    const size_t base = (size_t)bh * (TT * 1024) + 960;   // row 15 of each step
    const float* xkg = XK + base;
    const float* xvg = XV + base;

    float kc = (tid < 64) ? xkg[tid] : 0.f;
    float va = 0.f, vb = 0.f;
    if (w == 0) { va = xvg[lane]; vb = xvg[lane + 32]; }

    for (int t = 0; t < TT; t++) {
        // snapshot W,b at chunk boundary (pre-update)
        if ((t & (CHUNK-1)) == 0) {
            const int c = t >> 4;
            float* ws = g_Wsnap + ((size_t)bh * NCHUNK + c) * 4096;
            #pragma unroll
            for (int i = 0; i < 16; i++) {
                const int d = w*16 + i;
                ws[d*64 + lane]      = Wa[i];
                ws[d*64 + lane + 32] = Wb[i];
            }
            if (w == 0) {
                float* bs = g_bsnap + ((size_t)bh * NCHUNK + c) * 64;
                bs[lane] = bav; bs[lane + 32] = bbv;
            }
        }

        // prefetch next step row-15
        float kn = 0.f, nva = 0.f, nvb = 0.f;
        if (t + 1 < TT) {
            const size_t o = (size_t)(t+1) * 1024;
            if (tid < 64) kn = xkg[o + tid];
            if (w == 0) { nva = xvg[o + lane]; nvb = xvg[o + lane + 32]; }
        }

        if (tid < 64) xs[tid] = kc;
        __syncthreads();                                    // B1

        // el (redundant in every warp; off critical path until update)
        const float xa = xs[lane], xb = xs[lane + 32];
        float ss = xa*xa + xb*xb;
        #pragma unroll
        for (int m = 16; m >= 1; m >>= 1) ss += __shfl_xor_sync(~0u, ss, m);
        const float el = 0.01f / (1.0f + fmaxf(sqrtf(ss), 1e-6f));

        // partial matvec over this warp's 16 d-rows (cache xs slice)
        float x16[16];
        float za = 0.f, zb = 0.f;
        #pragma unroll
        for (int i = 0; i < 16; i++) {
            x16[i] = xs[w*16 + i];
            za = fmaf(x16[i], Wa[i], za);
            zb = fmaf(x16[i], Wb[i], zb);
        }
        pz[w][lane] = za; pz[w][lane + 32] = zb;
        __syncthreads();                                    // B2

        if (w == 0) {
            const float zA = bav + ((pz[0][lane] + pz[1][lane]) + (pz[2][lane] + pz[3][lane]));
            const float zB = bbv + ((pz[0][lane+32] + pz[1][lane+32]) + (pz[2][lane+32] + pz[3][lane+32]));
            float s1 = zA + zB;
            float s2 = zA*zA + zB*zB;
            #pragma unroll
            for (int m = 16; m >= 1; m >>= 1) {
                s1 += __shfl_xor_sync(~0u, s1, m);
                s2 += __shfl_xor_sync(~0u, s2, m);
            }
            const float mu  = s1 * 0.015625f;
            const float var = fmaf(-mu, mu, s2 * 0.015625f);
            const float r   = rsqrtf(var + 1e-6f);
            const float gza = 2.0f * (fmaf(ga, (zA-mu)*r, bea) - va + xa);
            const float gzb = 2.0f * (fmaf(gb, (zB-mu)*r, beb) - vb + xb);
            gs[lane] = gza; gs[lane + 32] = gzb;
            bav = fmaf(-el, gza, bav);
            bbv = fmaf(-el, gzb, bbv);
        }
        __syncthreads();                                    // B3

        // rank-1 update of local W rows
        const float ea = el * gs[lane], eb = el * gs[lane + 32];
        #pragma unroll
        for (int i = 0; i < 16; i++) {
            Wa[i] = fmaf(-ea, x16[i], Wa[i]);
            Wb[i] = fmaf(-eb, x16[i], Wb[i]);
        }
        __syncthreads();                                    // B4 (protect xs/gs)

        kc = kn; va = nva; vb = nvb;
    }
}

// ====== kernel 2: parallel chunk replay, paired steps (one W-pass / 2) ======
// dyn smem layout (floats):
#define OFF_XQ  4096                  // 4 buffers x 1088
#define OFF_XK  (4096 + 4352)
#define OFF_GZ  (4096 + 8704)
#define OFF_BB  (OFF_GZ + 1088)
#define OFF_ETA (OFF_BB + 64)         // 4 x 16
#define SMF     (OFF_ETA + 64)

__global__ __launch_bounds__(256)
void chunk_kernel(const float* __restrict__ XQ, const float* __restrict__ XK,
                  const float* __restrict__ XV, const float* __restrict__ gam,
                  const float* __restrict__ bet, float* __restrict__ out)
{
    extern __shared__ float sm[];
    float* const W  = sm;
    float* const GZ = sm + OFF_GZ;
    float* const BB = sm + OFF_BB;

    const int tid = threadIdx.x;
    const int c   = blockIdx.x;
    const int bh  = blockIdx.y;
    const int h   = bh & 15;
    const int k   = tid >> 4;
    const int q   = tid & 15;
    const int f0  = q << 2;
    const int sl  = k*ROWP + f0;

    const size_t base = (size_t)bh * (TT * 1024) + (size_t)c * (CHUNK * 1024);
    const float* xqg = XQ + base;
    const float* xkg = XK + base;
    const float* xvg = XV + base;
    float*       og  = out + base;

    // init from snapshot
    {
        const float* Ws = g_Wsnap + ((size_t)bh * NCHUNK + c) * 4096;
        #pragma unroll
        for (int i = 0; i < 4; i++)
            *(float4*)&W[i*1024 + tid*4] = *(const float4*)&Ws[i*1024 + tid*4];
        if (tid < 16) {
            const float* bs = g_bsnap + ((size_t)bh * NCHUNK + c) * 64;
            *(float4*)&BB[tid*4] = *(const float4*)&bs[tid*4];
        }
    }
    const float4 g4  = *(const float4*)&gam[h*64 + f0];
    const float4 be4 = *(const float4*)&bet[h*64 + f0];

    // stage pair-0 tiles (buffers 0,1) + eta
    #pragma unroll
    for (int s = 0; s < 2; s++) {
        const float4 tq = *(const float4*)&xqg[s*1024 + tid*4];
        const float4 tk = *(const float4*)&xkg[s*1024 + tid*4];
        *(float4*)&sm[OFF_XQ + s*1088 + sl] = tq;
        *(float4*)&sm[OFF_XK + s*1088 + sl] = tk;
        float ss = tk.x*tk.x + tk.y*tk.y + tk.z*tk.z + tk.w*tk.w;
        #pragma unroll
        for (int m = 8; m >= 1; m >>= 1) ss += __shfl_xor_sync(~0u, ss, m, 16);
        if (q == 0) sm[OFF_ETA + s*16 + k] = 0.01f / (1.0f + fmaxf(sqrtf(ss), 1e-6f));
    }
    __syncthreads();

    for (int p = 0; p < NPAIR; p++) {
        const int bA = (p & 1) * 2, bB = bA + 1;
        const int nA = ((p + 1) & 1) * 2, nB = nA + 1;
        const float* xqA = sm + OFF_XQ + bA*1088;
        const float* xkA_ = sm + OFF_XK + bA*1088;
        const float* xqB = sm + OFF_XQ + bB*1088;
        const float* xkB = sm + OFF_XK + bB*1088;

        // async stage next pair
        if (p + 1 < NPAIR) {
            const size_t o1 = (size_t)(2*p+2)*1024 + tid*4;
            const size_t o2 = o1 + 1024;
            CPA16((unsigned)__cvta_generic_to_shared(&sm[OFF_XQ + nA*1088 + sl]), xqg + o1);
            CPA16((unsigned)__cvta_generic_to_shared(&sm[OFF_XK + nA*1088 + sl]), xkg + o1);
            CPA16((unsigned)__cvta_generic_to_shared(&sm[OFF_XQ + nB*1088 + sl]), xqg + o2);
            CPA16((unsigned)__cvta_generic_to_shared(&sm[OFF_XK + nB*1088 + sl]), xkg + o2);
            CPCOMMIT();
        }
        // xv for both steps via LDG (consumed late; latency hides under main pass)
        const float4 cv  = *(const float4*)&xvg[(size_t)(2*p)*1024 + tid*4];
        const float4 cv1 = *(const float4*)&xvg[(size_t)(2*p+1)*1024 + tid*4];

        // em/el for both steps
        float em, el, em1, el1;
        {
            const float4 e0 = *(const float4*)&sm[OFF_ETA + bA*16 + 0];
            const float4 e1 = *(const float4*)&sm[OFF_ETA + bA*16 + 4];
            const float4 e2 = *(const float4*)&sm[OFF_ETA + bA*16 + 8];
            const float4 e3 = *(const float4*)&sm[OFF_ETA + bA*16 + 12];
            em = ((e0.x+e0.y+e0.z+e0.w) + (e1.x+e1.y+e1.z+e1.w)
                + (e2.x+e2.y+e2.z+e2.w) + (e3.x+e3.y+e3.z+e3.w)) * (1.0f/16.0f);
            el = e3.w;
            const float4 f0v = *(const float4*)&sm[OFF_ETA + bB*16 + 0];
            const float4 f1v = *(const float4*)&sm[OFF_ETA + bB*16 + 4];
            const float4 f2v = *(const float4*)&sm[OFF_ETA + bB*16 + 8];
            const float4 f3v = *(const float4*)&sm[OFF_ETA + bB*16 + 12];
            em1 = ((f0v.x+f0v.y+f0v.z+f0v.w) + (f1v.x+f1v.y+f1v.z+f1v.w)
                 + (f2v.x+f2v.y+f2v.z+f2v.w) + (f3v.x+f3v.y+f3v.z+f3v.w)) * (1.0f/16.0f);
            el1 = f3v.w;
        }

        // ---- one W-pass for BOTH steps of the pair ----
        float4 z, zd, zn, zdn;
        {
            const float4 b4 = *(const float4*)&BB[f0];
            z = b4; zd = b4; zn = b4; zdn = b4;
        }
        float a = 1.0f, an = 1.0f, dk = 0.f, dq = 0.f;
        #pragma unroll 4
        for (int j = 0; j < 16; j++) {
            const int d0 = j << 2;
            const float4 xkt = *(const float4*)&xkA_[k*ROWP + d0];
            const float4 xqt = *(const float4*)&xqA [k*ROWP + d0];
            const float4 xkn = *(const float4*)&xkB [k*ROWP + d0];
            const float4 xqn = *(const float4*)&xqB [k*ROWP + d0];
            const float4 xAt = *(const float4*)&xkA_[q*ROWP + d0];
            const float4 xAn = *(const float4*)&xkB [q*ROWP + d0];
            const float4 xF  = *(const float4*)&xkA_[15*ROWP + d0];   // xk15 of step t
            a  = fmaf(xqt.x, xAt.x, fmaf(xqt.y, xAt.y, fmaf(xqt.z, xAt.z, fmaf(xqt.w, xAt.w, a))));
            an = fmaf(xqn.x, xAn.x, fmaf(xqn.y, xAn.y, fmaf(xqn.z, xAn.z, fmaf(xqn.w, xAn.w, an))));
            dk = fmaf(xkn.x, xF.x, fmaf(xkn.y, xF.y, fmaf(xkn.z, xF.z, fmaf(xkn.w, xF.w, dk))));
            dq = fmaf(xqn.x, xF.x, fmaf(xqn.y, xF.y, fmaf(xqn.z, xF.z, fmaf(xqn.w, xF.w, dq))));
            #pragma unroll
            for (int i = 0; i < 4; i++) {
                const float4 w4 = *(const float4*)&W[(d0+i)*64 + f0];
                const float kt = (&xkt.x)[i], qt = (&xqt.x)[i];
                const float kn2 = (&xkn.x)[i], qn2 = (&xqn.x)[i];
                z.x   = fmaf(kt,  w4.x, z.x);   z.y   = fmaf(kt,  w4.y, z.y);
                z.z   = fmaf(kt,  w4.z, z.z);   z.w   = fmaf(kt,  w4.w, z.w);
                zd.x  = fmaf(qt,  w4.x, zd.x);  zd.y  = fmaf(qt,  w4.y, zd.y);
                zd.z  = fmaf(qt,  w4.z, zd.z);  zd.w  = fmaf(qt,  w4.w, zd.w);
                zn.x  = fmaf(kn2, w4.x, zn.x);  zn.y  = fmaf(kn2, w4.y, zn.y);
                zn.z  = fmaf(kn2, w4.z, zn.z);  zn.w  = fmaf(kn2, w4.w, zn.w);
                zdn.x = fmaf(qn2, w4.x, zdn.x); zdn.y = fmaf(qn2, w4.y, zdn.y);
                zdn.z = fmaf(qn2, w4.z, zdn.z); zdn.w = fmaf(qn2, w4.w, zdn.w);
            }
        }

        // ---- epilogue step t = 2p ----
        const float4 ck = *(const float4*)&xkA_[sl];
        {
            float s1 = z.x + z.y + z.z + z.w;
            float s2 = z.x*z.x + z.y*z.y + z.z*z.z + z.w*z.w;
            #pragma unroll
            for (int m = 8; m >= 1; m >>= 1) {
                s1 += __shfl_xor_sync(~0u, s1, m, 16);
                s2 += __shfl_xor_sync(~0u, s2, m, 16);
            }
            const float mu  = s1 * 0.015625f;
            const float var = fmaf(-mu, mu, s2 * 0.015625f);
            const float r   = rsqrtf(var + 1e-6f);
            float4 gz;
            gz.x = 2.0f * (fmaf(g4.x, (z.x-mu)*r, be4.x) - cv.x + ck.x);
            gz.y = 2.0f * (fmaf(g4.y, (z.y-mu)*r, be4.y) - cv.y + ck.y);
            gz.z = 2.0f * (fmaf(g4.z, (z.z-mu)*r, be4.z) - cv.z + ck.z);
            gz.w = 2.0f * (fmaf(g4.w, (z.w-mu)*r, be4.w) - cv.w + ck.w);
            *(float4*)&GZ[sl] = gz;
        }
        __syncthreads();                                    // bar1

        const float4 gl = *(const float4*)&GZ[15*ROWP + f0];
        // deferred fix: step t+1 accumulators -> true W_{t+1}, b_{t+1}
        {
            const float fk = -el * (dk + 1.0f);
            const float fq2 = -el * (dq + 1.0f);
            zn.x  = fmaf(fk,  gl.x, zn.x);  zn.y  = fmaf(fk,  gl.y, zn.y);
            zn.z  = fmaf(fk,  gl.z, zn.z);  zn.w  = fmaf(fk,  gl.w, zn.w);
            zdn.x = fmaf(fq2, gl.x, zdn.x); zdn.y = fmaf(fq2, gl.y, zdn.y);
            zdn.z = fmaf(fq2, gl.z, zdn.z); zdn.w = fmaf(fq2, gl.w, zdn.w);
        }
        // correction + LN2 + out, step t
        {
            float4 cc = make_float4(0.f,0.f,0.f,0.f);
            #pragma unroll
            for (int kp = 0; kp < 16; kp++) {
                const float av  = __shfl_sync(~0u, a, kp, 16);
                const float4 gv = *(const float4*)&GZ[kp*ROWP + f0];
                cc.x = fmaf(av, gv.x, cc.x); cc.y = fmaf(av, gv.y, cc.y);
                cc.z = fmaf(av, gv.z, cc.z); cc.w = fmaf(av, gv.w, cc.w);
            }
            zd.x = fmaf(-em, cc.x, zd.x); zd.y = fmaf(-em, cc.y, zd.y);
            zd.z = fmaf(-em, cc.z, zd.z); zd.w = fmaf(-em, cc.w, zd.w);
            float t1 = zd.x + zd.y + zd.z + zd.w;
            float t2 = zd.x*zd.x + zd.y*zd.y + zd.z*zd.z + zd.w*zd.w;
            #pragma unroll
            for (int m = 8; m >= 1; m >>= 1) {
                t1 += __shfl_xor_sync(~0u, t1, m, 16);
                t2 += __shfl_xor_sync(~0u, t2, m, 16);
            }
            const float mu2  = t1 * 0.015625f;
            const float var2 = fmaf(-mu2, mu2, t2 * 0.015625f);
            const float r2   = rsqrtf(var2 + 1e-6f);
            const float4 cq = *(const float4*)&xqA[sl];
            float4 o;
            o.x = cq.x + fmaf(g4.x, (zd.x-mu2)*r2, be4.x);
            o.y = cq.y + fmaf(g4.y, (zd.y-mu2)*r2, be4.y);
            o.z = cq.z + fmaf(g4.z, (zd.z-mu2)*r2, be4.z);
            o.w = cq.w + fmaf(g4.w, (zd.w-mu2)*r2, be4.w);
            *(float4*)&og[(size_t)(2*p)*1024 + tid*4] = o;
        }
        __syncthreads();                                    // bar2 (GZ free)

        // ---- epilogue step t+1 ----
        const float4 ck1 = *(const float4*)&xkB[sl];
        {
            float s1 = zn.x + zn.y + zn.z + zn.w;
            float s2 = zn.x*zn.x + zn.y*zn.y + zn.z*zn.z + zn.w*zn.w;
            #pragma unroll
            for (int m = 8; m >= 1; m >>= 1) {
                s1 += __shfl_xor_sync(~0u, s1, m, 16);
                s2 += __shfl_xor_sync(~0u, s2, m, 16);
            }
            const float mu  = s1 * 0.015625f;
            const float var = fmaf(-mu, mu, s2 * 0.015625f);
            const float r   = rsqrtf(var + 1e-6f);
            float4 gz;
            gz.x = 2.0f * (fmaf(g4.x, (zn.x-mu)*r, be4.x) - cv1.x + ck1.x);
            gz.y = 2.0f * (fmaf(g4.y, (zn.y-mu)*r, be4.y) - cv1.y + ck1.y);
            gz.z = 2.0f * (fmaf(g4.z, (zn.z-mu)*r, be4.z) - cv1.z + ck1.z);
            gz.w = 2.0f * (fmaf(g4.w, (zn.w-mu)*r, be4.w) - cv1.w + ck1.w);
            *(float4*)&GZ[sl] = gz;
        }
        __syncthreads();                                    // bar3
        {
            float4 cc = make_float4(0.f,0.f,0.f,0.f);
            #pragma unroll
            for (int kp = 0; kp < 16; kp++) {
                const float av  = __shfl_sync(~0u, an, kp, 16);
                const float4 gv = *(const float4*)&GZ[kp*ROWP + f0];
                cc.x = fmaf(av, gv.x, cc.x); cc.y = fmaf(av, gv.y, cc.y);
                cc.z = fmaf(av, gv.z, cc.z); cc.w = fmaf(av, gv.w, cc.w);
            }
            zdn.x = fmaf(-em1, cc.x, zdn.x); zdn.y = fmaf(-em1, cc.y, zdn.y);
            zdn.z = fmaf(-em1, cc.z, zdn.z); zdn.w = fmaf(-em1, cc.w, zdn.w);
            float t1 = zdn.x + zdn.y + zdn.z + zdn.w;
            float t2 = zdn.x*zdn.x + zdn.y*zdn.y + zdn.z*zdn.z + zdn.w*zdn.w;
            #pragma unroll
            for (int m = 8; m >= 1; m >>= 1) {
                t1 += __shfl_xor_sync(~0u, t1, m, 16);
                t2 += __shfl_xor_sync(~0u, t2, m, 16);
            }
            const float mu2  = t1 * 0.015625f;
            const float var2 = fmaf(-mu2, mu2, t2 * 0.015625f);
            const float r2   = rsqrtf(var2 + 1e-6f);
            const float4 cq1 = *(const float4*)&xqB[sl];
            float4 o;
            o.x = cq1.x + fmaf(g4.x, (zdn.x-mu2)*r2, be4.x);
            o.y = cq1.y + fmaf(g4.y, (zdn.y-mu2)*r2, be4.y);
            o.z = cq1.z + fmaf(g4.z, (zdn.z-mu2)*r2, be4.z);
            o.w = cq1.w + fmaf(g4.w, (zdn.w-mu2)*r2, be4.w);
            *(float4*)&og[(size_t)(2*p+1)*1024 + tid*4] = o;
        }

        // ---- rank-2 carry update + next-pair eta (skip on last pair) ----
        if (p + 1 < NPAIR) {
            const float4 gl1 = *(const float4*)&GZ[15*ROWP + f0];
            #pragma unroll
            for (int jj = 0; jj < 4; jj++) {
                const int d = k + 16*jj;
                const float cf  = -el  * xkA_[15*ROWP + d];
                const float cf1 = -el1 * xkB [15*ROWP + d];
                float4 w4 = *(float4*)&W[d*64 + f0];
                w4.x = fmaf(cf, gl.x, fmaf(cf1, gl1.x, w4.x));
                w4.y = fmaf(cf, gl.y, fmaf(cf1, gl1.y, w4.y));
                w4.z = fmaf(cf, gl.z, fmaf(cf1, gl1.z, w4.z));
                w4.w = fmaf(cf, gl.w, fmaf(cf1, gl1.w, w4.w));
                *(float4*)&W[d*64 + f0] = w4;
            }
            if (tid < 16) {
                float4 bv = *(float4*)&BB[f0];
                bv.x = fmaf(-el, gl.x, fmaf(-el1, gl1.x, bv.x));
                bv.y = fmaf(-el, gl.y, fmaf(-el1, gl1.y, bv.y));
                bv.z = fmaf(-el, gl.z, fmaf(-el1, gl1.z, bv.z));
                bv.w = fmaf(-el, gl.w, fmaf(-el1, gl1.w, bv.w));
                *(float4*)&BB[f0] = bv;
            }
            CPWAIT0();
            #pragma unroll
            for (int s = 0; s < 2; s++) {
                const int nb = (s == 0) ? nA : nB;
                const float4 tk = *(const float4*)&sm[OFF_XK + nb*1088 + sl];
                float ss = tk.x*tk.x + tk.y*tk.y + tk.z*tk.z + tk.w*tk.w;
                #pragma unroll
                for (int m = 8; m >= 1; m >>= 1) ss += __shfl_xor_sync(~0u, ss, m, 16);
                if (q == 0) sm[OFF_ETA + nb*16 + k] = 0.01f / (1.0f + fmaxf(sqrtf(ss), 1e-6f));
            }
            __syncthreads();                                // bar4
        }
    }
}

extern "C" void kernel_launch(void* const* d_in, const int* in_sizes, int n_in,
                              void* d_out, int out_size) {
    const float* XQ  = (const float*)d_in[0];
    const float* XK  = (const float*)d_in[1];
    const float* XV  = (const float*)d_in[2];
    const float* W1  = (const float*)d_in[3];
    const float* b1  = (const float*)d_in[4];
    const float* gam = (const float*)d_in[5];
    const float* bet = (const float*)d_in[6];
    float* out = (float*)d_out;

    const int nbh  = in_sizes[0] / (TT * 16 * 64);   // B*H = 64
    const int smem = SMF * (int)sizeof(float);       // ~56 KB
    static int configured = 0;
    if (!configured) {
        cudaFuncSetAttribute(chunk_kernel, cudaFuncAttributeMaxDynamicSharedMemorySize, smem);
        configured = 1;
    }
    scan_kernel<<<nbh, 128>>>(XK, XV, W1, b1, gam, bet);
    chunk_kernel<<<dim3(NCHUNK, nbh), 256, smem>>>(XQ, XK, XV, gam, bet, out);
}

// round 13
// speedup vs baseline: 2.2694x; 1.1522x over previous
#include <cuda_runtime.h>

#define TT     512
#define CHUNK  16
#define NPAIR  8
#define NCHUNK 32
#define NBH    64
#define ROWP   68

__device__ float g_Wsnap[(size_t)NBH * NCHUNK * 4096];
__device__ float g_bsnap[(size_t)NBH * NCHUNK * 64];
__device__ int   g_prog[NBH];

#define CPA16(saddr, gptr) \
    asm volatile("cp.async.cg.shared.global [%0], [%1], 16;" :: "r"(saddr), "l"(gptr))
#define CPCOMMIT() asm volatile("cp.async.commit_group;")
#define CPWAIT0()  asm volatile("cp.async.wait_group 0;")

// chunk-role dyn smem layout (floats)
#define OFF_XQ  4096                  // 4 buffers x 1088
#define OFF_XK  (OFF_XQ + 4352)
#define OFF_GZ  (OFF_XK + 4352)
#define OFF_BB  (OFF_GZ + 1088)
#define OFF_ETA (OFF_BB + 64)         // 4 x 16
#define SMF     (OFF_ETA + 64)        // 14016 floats = 56 KB

__global__ void reset_kernel() {
    if (threadIdx.x < NBH) g_prog[threadIdx.x] = 0;
}

// ================= scan role: sequential rank-1 scan, 4-warp d-split ========
__device__ __forceinline__
void scan_role(float* sm, int bh,
               const float* __restrict__ XK, const float* __restrict__ XV,
               const float* __restrict__ W1, const float* __restrict__ b1,
               const float* __restrict__ gam, const float* __restrict__ bet)
{
    float* const xs = sm;            // [2][64]
    float* const pz = sm + 128;      // [4][64]
    float* const gs = sm + 384;      // [2][64]

    const int tid  = threadIdx.x;
    const int lane = tid & 31;
    const int w    = tid >> 5;
    const int h    = bh & 15;

    float Wa[16], Wb[16];
    {
        const float* Wg = W1 + (size_t)h * 4096;
        #pragma unroll
        for (int i = 0; i < 16; i++) {
            const int d = w*16 + i;
            Wa[i] = Wg[d*64 + lane];
            Wb[i] = Wg[d*64 + lane + 32];
        }
    }
    float bav = b1[h*64 + lane], bbv = b1[h*64 + lane + 32];
    const float ga  = gam[h*64 + lane], gb  = gam[h*64 + lane + 32];
    const float bea = bet[h*64 + lane], beb = bet[h*64 + lane + 32];

    const size_t base = (size_t)bh * (TT * 1024) + 960;   // row 15 of each step
    const float* xkg = XK + base;
    const float* xvg = XV + base;

    float kc = (tid < 64) ? xkg[tid] : 0.f;
    float va = 0.f, vb = 0.f;
    if (w == 0) { va = xvg[lane]; vb = xvg[lane + 32]; }

    for (int t = 0; t < TT; t++) {
        const int pr = t & 1;

        // snapshot W,b at chunk boundary (pre-update)
        if ((t & (CHUNK-1)) == 0) {
            const int c = t >> 4;
            float* ws = g_Wsnap + ((size_t)bh * NCHUNK + c) * 4096;
            #pragma unroll
            for (int i = 0; i < 16; i++) {
                const int d = w*16 + i;
                ws[d*64 + lane]      = Wa[i];
                ws[d*64 + lane + 32] = Wb[i];
            }
            if (w == 0) {
                float* bs = g_bsnap + ((size_t)bh * NCHUNK + c) * 64;
                bs[lane] = bav; bs[lane + 32] = bbv;
            }
        }

        // prefetch next step row-15
        float kn = 0.f, nva = 0.f, nvb = 0.f;
        if (t + 1 < TT) {
            const size_t o = (size_t)(t+1) * 1024;
            if (tid < 64) kn = xkg[o + tid];
            if (w == 0) { nva = xvg[o + lane]; nvb = xvg[o + lane + 32]; }
        }

        if (tid < 64) xs[pr*64 + tid] = kc;
        __syncthreads();                                    // B1

        // publish snapshot (writes complete at B1) -> release flag
        if ((t & (CHUNK-1)) == 0 && tid == 0) {
            __threadfence();
            atomicExch(&g_prog[bh], (t >> 4) + 1);
        }

        // el (redundant in every warp)
        const float xa = xs[pr*64 + lane], xb = xs[pr*64 + lane + 32];
        float ss = xa*xa + xb*xb;
        #pragma unroll
        for (int m = 16; m >= 1; m >>= 1) ss += __shfl_xor_sync(~0u, ss, m);
        const float el = 0.01f / (1.0f + fmaxf(sqrtf(ss), 1e-6f));

        // partial matvec over this warp's 16 d-rows
        float x16[16];
        float za = 0.f, zb = 0.f;
        #pragma unroll
        for (int i = 0; i < 16; i++) {
            x16[i] = xs[pr*64 + w*16 + i];
            za = fmaf(x16[i], Wa[i], za);
            zb = fmaf(x16[i], Wb[i], zb);
        }
        pz[w*64 + lane] = za; pz[w*64 + lane + 32] = zb;
        __syncthreads();                                    // B2

        if (w == 0) {
            const float zA = bav + ((pz[lane] + pz[64+lane]) + (pz[128+lane] + pz[192+lane]));
            const float zB = bbv + ((pz[lane+32] + pz[64+lane+32]) + (pz[128+lane+32] + pz[192+lane+32]));
            float s1 = zA + zB;
            float s2 = zA*zA + zB*zB;
            #pragma unroll
            for (int m = 16; m >= 1; m >>= 1) {
                s1 += __shfl_xor_sync(~0u, s1, m);
                s2 += __shfl_xor_sync(~0u, s2, m);
            }
            const float mu  = s1 * 0.015625f;
            const float var = fmaf(-mu, mu, s2 * 0.015625f);
            const float r   = rsqrtf(var + 1e-6f);
            const float gza = 2.0f * (fmaf(ga, (zA-mu)*r, bea) - va + xa);
            const float gzb = 2.0f * (fmaf(gb, (zB-mu)*r, beb) - vb + xb);
            gs[pr*64 + lane] = gza; gs[pr*64 + lane + 32] = gzb;
            bav = fmaf(-el, gza, bav);
            bbv = fmaf(-el, gzb, bbv);
        }
        __syncthreads();                                    // B3

        // rank-1 update of local W rows (xs/gs parity-buffered: no 4th barrier)
        const float ea = el * gs[pr*64 + lane], eb = el * gs[pr*64 + lane + 32];
        #pragma unroll
        for (int i = 0; i < 16; i++) {
            Wa[i] = fmaf(-ea, x16[i], Wa[i]);
            Wb[i] = fmaf(-eb, x16[i], Wb[i]);
        }

        kc = kn; va = nva; vb = nvb;
    }
    // final flag so no consumer can hang (all snapshots written)
    if (tid == 0) { __threadfence(); atomicExch(&g_prog[bh], NCHUNK + 1); }
}

// ====== chunk role: parallel chunk replay, paired steps (one W-pass / 2) ====
__device__ __forceinline__
void chunk_role(float* sm, int c, int bh,
                const float* __restrict__ XQ, const float* __restrict__ XK,
                const float* __restrict__ XV, const float* __restrict__ gam,
                const float* __restrict__ bet, float* __restrict__ out)
{
    float* const W  = sm;
    float* const GZ = sm + OFF_GZ;
    float* const BB = sm + OFF_BB;

    const int tid = threadIdx.x;
    const int h   = bh & 15;
    const int k   = tid >> 4;
    const int q   = tid & 15;
    const int f0  = q << 2;
    const int sl  = k*ROWP + f0;

    // ---- spin until snapshot c is published ----
    if (tid == 0) {
        volatile int* f = &g_prog[bh];
        while (*f < c + 1) __nanosleep(256);
    }
    __syncthreads();
    __threadfence();   // acquire: order snapshot reads after flag observation

    const size_t base = (size_t)bh * (TT * 1024) + (size_t)c * (CHUNK * 1024);
    const float* xqg = XQ + base;
    const float* xkg = XK + base;
    const float* xvg = XV + base;
    float*       og  = out + base;

    {
        const float* Ws = g_Wsnap + ((size_t)bh * NCHUNK + c) * 4096;
        #pragma unroll
        for (int i = 0; i < 4; i++)
            *(float4*)&W[i*1024 + tid*4] = *(const float4*)&Ws[i*1024 + tid*4];
        if (tid < 16) {
            const float* bs = g_bsnap + ((size_t)bh * NCHUNK + c) * 64;
            *(float4*)&BB[tid*4] = *(const float4*)&bs[tid*4];
        }
    }
    const float4 g4  = *(const float4*)&gam[h*64 + f0];
    const float4 be4 = *(const float4*)&bet[h*64 + f0];

    #pragma unroll
    for (int s = 0; s < 2; s++) {
        const float4 tq = *(const float4*)&xqg[s*1024 + tid*4];
        const float4 tk = *(const float4*)&xkg[s*1024 + tid*4];
        *(float4*)&sm[OFF_XQ + s*1088 + sl] = tq;
        *(float4*)&sm[OFF_XK + s*1088 + sl] = tk;
        float ss = tk.x*tk.x + tk.y*tk.y + tk.z*tk.z + tk.w*tk.w;
        #pragma unroll
        for (int m = 8; m >= 1; m >>= 1) ss += __shfl_xor_sync(~0u, ss, m, 16);
        if (q == 0) sm[OFF_ETA + s*16 + k] = 0.01f / (1.0f + fmaxf(sqrtf(ss), 1e-6f));
    }
    __syncthreads();

    for (int p = 0; p < NPAIR; p++) {
        const int bA = (p & 1) * 2, bB = bA + 1;
        const int nA = ((p + 1) & 1) * 2, nB = nA + 1;
        const float* xqA  = sm + OFF_XQ + bA*1088;
        const float* xkA_ = sm + OFF_XK + bA*1088;
        const float* xqB  = sm + OFF_XQ + bB*1088;
        const float* xkB  = sm + OFF_XK + bB*1088;

        if (p + 1 < NPAIR) {
            const size_t o1 = (size_t)(2*p+2)*1024 + tid*4;
            const size_t o2 = o1 + 1024;
            CPA16((unsigned)__cvta_generic_to_shared(&sm[OFF_XQ + nA*1088 + sl]), xqg + o1);
            CPA16((unsigned)__cvta_generic_to_shared(&sm[OFF_XK + nA*1088 + sl]), xkg + o1);
            CPA16((unsigned)__cvta_generic_to_shared(&sm[OFF_XQ + nB*1088 + sl]), xqg + o2);
            CPA16((unsigned)__cvta_generic_to_shared(&sm[OFF_XK + nB*1088 + sl]), xkg + o2);
            CPCOMMIT();
        }
        const float4 cv  = *(const float4*)&xvg[(size_t)(2*p)*1024 + tid*4];
        const float4 cv1 = *(const float4*)&xvg[(size_t)(2*p+1)*1024 + tid*4];

        float em, el, em1, el1;
        {
            const float4 e0 = *(const float4*)&sm[OFF_ETA + bA*16 + 0];
            const float4 e1 = *(const float4*)&sm[OFF_ETA + bA*16 + 4];
            const float4 e2 = *(const float4*)&sm[OFF_ETA + bA*16 + 8];
            const float4 e3 = *(const float4*)&sm[OFF_ETA + bA*16 + 12];
            em = ((e0.x+e0.y+e0.z+e0.w) + (e1.x+e1.y+e1.z+e1.w)
                + (e2.x+e2.y+e2.z+e2.w) + (e3.x+e3.y+e3.z+e3.w)) * (1.0f/16.0f);
            el = e3.w;
            const float4 f0v = *(const float4*)&sm[OFF_ETA + bB*16 + 0];
            const float4 f1v = *(const float4*)&sm[OFF_ETA + bB*16 + 4];
            const float4 f2v = *(const float4*)&sm[OFF_ETA + bB*16 + 8];
            const float4 f3v = *(const float4*)&sm[OFF_ETA + bB*16 + 12];
            em1 = ((f0v.x+f0v.y+f0v.z+f0v.w) + (f1v.x+f1v.y+f1v.z+f1v.w)
                 + (f2v.x+f2v.y+f2v.z+f2v.w) + (f3v.x+f3v.y+f3v.z+f3v.w)) * (1.0f/16.0f);
            el1 = f3v.w;
        }

        float4 z, zd, zn, zdn;
        {
            const float4 b4 = *(const float4*)&BB[f0];
            z = b4; zd = b4; zn = b4; zdn = b4;
        }
        float a = 1.0f, an = 1.0f, dk = 0.f, dq = 0.f;
        #pragma unroll 4
        for (int j = 0; j < 16; j++) {
            const int d0 = j << 2;
            const float4 xkt = *(const float4*)&xkA_[k*ROWP + d0];
            const float4 xqt = *(const float4*)&xqA [k*ROWP + d0];
            const float4 xkn = *(const float4*)&xkB [k*ROWP + d0];
            const float4 xqn = *(const float4*)&xqB [k*ROWP + d0];
            const float4 xAt = *(const float4*)&xkA_[q*ROWP + d0];
            const float4 xAn = *(const float4*)&xkB [q*ROWP + d0];
            const float4 xF  = *(const float4*)&xkA_[15*ROWP + d0];
            a  = fmaf(xqt.x, xAt.x, fmaf(xqt.y, xAt.y, fmaf(xqt.z, xAt.z, fmaf(xqt.w, xAt.w, a))));
            an = fmaf(xqn.x, xAn.x, fmaf(xqn.y, xAn.y, fmaf(xqn.z, xAn.z, fmaf(xqn.w, xAn.w, an))));
            dk = fmaf(xkn.x, xF.x, fmaf(xkn.y, xF.y, fmaf(xkn.z, xF.z, fmaf(xkn.w, xF.w, dk))));
            dq = fmaf(xqn.x, xF.x, fmaf(xqn.y, xF.y, fmaf(xqn.z, xF.z, fmaf(xqn.w, xF.w, dq))));
            #pragma unroll
            for (int i = 0; i < 4; i++) {
                const float4 w4 = *(const float4*)&W[(d0+i)*64 + f0];
                const float kt  = (&xkt.x)[i], qt  = (&xqt.x)[i];
                const float kn2 = (&xkn.x)[i], qn2 = (&xqn.x)[i];
                z.x   = fmaf(kt,  w4.x, z.x);   z.y   = fmaf(kt,  w4.y, z.y);
                z.z   = fmaf(kt,  w4.z, z.z);   z.w   = fmaf(kt,  w4.w, z.w);
                zd.x  = fmaf(qt,  w4.x, zd.x);  zd.y  = fmaf(qt,  w4.y, zd.y);
                zd.z  = fmaf(qt,  w4.z, zd.z);  zd.w  = fmaf(qt,  w4.w, zd.w);
                zn.x  = fmaf(kn2, w4.x, zn.x);  zn.y  = fmaf(kn2, w4.y, zn.y);
                zn.z  = fmaf(kn2, w4.z, zn.z);  zn.w  = fmaf(kn2, w4.w, zn.w);
                zdn.x = fmaf(qn2, w4.x, zdn.x); zdn.y = fmaf(qn2, w4.y, zdn.y);
                zdn.z = fmaf(qn2, w4.z, zdn.z); zdn.w = fmaf(qn2, w4.w, zdn.w);
            }
        }

        // epilogue step t = 2p
        const float4 ck = *(const float4*)&xkA_[sl];
        {
            float s1 = z.x + z.y + z.z + z.w;
            float s2 = z.x*z.x + z.y*z.y + z.z*z.z + z.w*z.w;
            #pragma unroll
            for (int m = 8; m >= 1; m >>= 1) {
                s1 += __shfl_xor_sync(~0u, s1, m, 16);
                s2 += __shfl_xor_sync(~0u, s2, m, 16);
            }
            const float mu  = s1 * 0.015625f;
            const float var = fmaf(-mu, mu, s2 * 0.015625f);
            const float r   = rsqrtf(var + 1e-6f);
            float4 gz;
            gz.x = 2.0f * (fmaf(g4.x, (z.x-mu)*r, be4.x) - cv.x + ck.x);
            gz.y = 2.0f * (fmaf(g4.y, (z.y-mu)*r, be4.y) - cv.y + ck.y);
            gz.z = 2.0f * (fmaf(g4.z, (z.z-mu)*r, be4.z) - cv.z + ck.z);
            gz.w = 2.0f * (fmaf(g4.w, (z.w-mu)*r, be4.w) - cv.w + ck.w);
            *(float4*)&GZ[sl] = gz;
        }
        __syncthreads();

        const float4 gl = *(const float4*)&GZ[15*ROWP + f0];
        {
            const float fk  = -el * (dk + 1.0f);
            const float fq2 = -el * (dq + 1.0f);
            zn.x  = fmaf(fk,  gl.x, zn.x);  zn.y  = fmaf(fk,  gl.y, zn.y);
            zn.z  = fmaf(fk,  gl.z, zn.z);  zn.w  = fmaf(fk,  gl.w, zn.w);
            zdn.x = fmaf(fq2, gl.x, zdn.x); zdn.y = fmaf(fq2, gl.y, zdn.y);
            zdn.z = fmaf(fq2, gl.z, zdn.z); zdn.w = fmaf(fq2, gl.w, zdn.w);
        }
        {
            float4 cc = make_float4(0.f,0.f,0.f,0.f);
            #pragma unroll
            for (int kp = 0; kp < 16; kp++) {
                const float av  = __shfl_sync(~0u, a, kp, 16);
                const float4 gv = *(const float4*)&GZ[kp*ROWP + f0];
                cc.x = fmaf(av, gv.x, cc.x); cc.y = fmaf(av, gv.y, cc.y);
                cc.z = fmaf(av, gv.z, cc.z); cc.w = fmaf(av, gv.w, cc.w);
            }
            zd.x = fmaf(-em, cc.x, zd.x); zd.y = fmaf(-em, cc.y, zd.y);
            zd.z = fmaf(-em, cc.z, zd.z); zd.w = fmaf(-em, cc.w, zd.w);
            float t1 = zd.x + zd.y + zd.z + zd.w;
            float t2 = zd.x*zd.x + zd.y*zd.y + zd.z*zd.z + zd.w*zd.w;
            #pragma unroll
            for (int m = 8; m >= 1; m >>= 1) {
                t1 += __shfl_xor_sync(~0u, t1, m, 16);
                t2 += __shfl_xor_sync(~0u, t2, m, 16);
            }
            const float mu2  = t1 * 0.015625f;
            const float var2 = fmaf(-mu2, mu2, t2 * 0.015625f);
            const float r2   = rsqrtf(var2 + 1e-6f);
            const float4 cq = *(const float4*)&xqA[sl];
            float4 o;
            o.x = cq.x + fmaf(g4.x, (zd.x-mu2)*r2, be4.x);
            o.y = cq.y + fmaf(g4.y, (zd.y-mu2)*r2, be4.y);
            o.z = cq.z + fmaf(g4.z, (zd.z-mu2)*r2, be4.z);
            o.w = cq.w + fmaf(g4.w, (zd.w-mu2)*r2, be4.w);
            *(float4*)&og[(size_t)(2*p)*1024 + tid*4] = o;
        }
        __syncthreads();

        // epilogue step t+1
        const float4 ck1 = *(const float4*)&xkB[sl];
        {
            float s1 = zn.x + zn.y + zn.z + zn.w;
            float s2 = zn.x*zn.x + zn.y*zn.y + zn.z*zn.z + zn.w*zn.w;
            #pragma unroll
            for (int m = 8; m >= 1; m >>= 1) {
                s1 += __shfl_xor_sync(~0u, s1, m, 16);
                s2 += __shfl_xor_sync(~0u, s2, m, 16);
            }
            const float mu  = s1 * 0.015625f;
            const float var = fmaf(-mu, mu, s2 * 0.015625f);
            const float r   = rsqrtf(var + 1e-6f);
            float4 gz;
            gz.x = 2.0f * (fmaf(g4.x, (zn.x-mu)*r, be4.x) - cv1.x + ck1.x);
            gz.y = 2.0f * (fmaf(g4.y, (zn.y-mu)*r, be4.y) - cv1.y + ck1.y);
            gz.z = 2.0f * (fmaf(g4.z, (zn.z-mu)*r, be4.z) - cv1.z + ck1.z);
            gz.w = 2.0f * (fmaf(g4.w, (zn.w-mu)*r, be4.w) - cv1.w + ck1.w);
            *(float4*)&GZ[sl] = gz;
        }
        __syncthreads();
        {
            float4 cc = make_float4(0.f,0.f,0.f,0.f);
            #pragma unroll
            for (int kp = 0; kp < 16; kp++) {
                const float av  = __shfl_sync(~0u, an, kp, 16);
                const float4 gv = *(const float4*)&GZ[kp*ROWP + f0];
                cc.x = fmaf(av, gv.x, cc.x); cc.y = fmaf(av, gv.y, cc.y);
                cc.z = fmaf(av, gv.z, cc.z); cc.w = fmaf(av, gv.w, cc.w);
            }
            zdn.x = fmaf(-em1, cc.x, zdn.x); zdn.y = fmaf(-em1, cc.y, zdn.y);
            zdn.z = fmaf(-em1, cc.z, zdn.z); zdn.w = fmaf(-em1, cc.w, zdn.w);
            float t1 = zdn.x + zdn.y + zdn.z + zdn.w;
            float t2 = zdn.x*zdn.x + zdn.y*zdn.y + zdn.z*zdn.z + zdn.w*zdn.w;
            #pragma unroll
            for (int m = 8; m >= 1; m >>= 1) {
                t1 += __shfl_xor_sync(~0u, t1, m, 16);
                t2 += __shfl_xor_sync(~0u, t2, m, 16);
            }
            const float mu2  = t1 * 0.015625f;
            const float var2 = fmaf(-mu2, mu2, t2 * 0.015625f);
            const float r2   = rsqrtf(var2 + 1e-6f);
            const float4 cq1 = *(const float4*)&xqB[sl];
            float4 o;
            o.x = cq1.x + fmaf(g4.x, (zdn.x-mu2)*r2, be4.x);
            o.y = cq1.y + fmaf(g4.y, (zdn.y-mu2)*r2, be4.y);
            o.z = cq1.z + fmaf(g4.z, (zdn.z-mu2)*r2, be4.z);
            o.w = cq1.w + fmaf(g4.w, (zdn.w-mu2)*r2, be4.w);
            *(float4*)&og[(size_t)(2*p+1)*1024 + tid*4] = o;
        }

        if (p + 1 < NPAIR) {
            const float4 gl1 = *(const float4*)&GZ[15*ROWP + f0];
            #pragma unroll
            for (int jj = 0; jj < 4; jj++) {
                const int d = k + 16*jj;
                const float cf  = -el  * xkA_[15*ROWP + d];
                const float cf1 = -el1 * xkB [15*ROWP + d];
                float4 w4 = *(float4*)&W[d*64 + f0];
                w4.x = fmaf(cf, gl.x, fmaf(cf1, gl1.x, w4.x));
                w4.y = fmaf(cf, gl.y, fmaf(cf1, gl1.y, w4.y));
                w4.z = fmaf(cf, gl.z, fmaf(cf1, gl1.z, w4.z));
                w4.w = fmaf(cf, gl.w, fmaf(cf1, gl1.w, w4.w));
                *(float4*)&W[d*64 + f0] = w4;
            }
            if (tid < 16) {
                float4 bv = *(float4*)&BB[f0];
                bv.x = fmaf(-el, gl.x, fmaf(-el1, gl1.x, bv.x));
                bv.y = fmaf(-el, gl.y, fmaf(-el1, gl1.y, bv.y));
                bv.z = fmaf(-el, gl.z, fmaf(-el1, gl1.z, bv.z));
                bv.w = fmaf(-el, gl.w, fmaf(-el1, gl1.w, bv.w));
                *(float4*)&BB[f0] = bv;
            }
            CPWAIT0();
            #pragma unroll
            for (int s = 0; s < 2; s++) {
                const int nb = (s == 0) ? nA : nB;
                const float4 tk = *(const float4*)&sm[OFF_XK + nb*1088 + sl];
                float ss = tk.x*tk.x + tk.y*tk.y + tk.z*tk.z + tk.w*tk.w;
                #pragma unroll
                for (int m = 8; m >= 1; m >>= 1) ss += __shfl_xor_sync(~0u, ss, m, 16);
                if (q == 0) sm[OFF_ETA + nb*16 + k] = 0.01f / (1.0f + fmaxf(sqrtf(ss), 1e-6f));
            }
            __syncthreads();
        }
    }
}

// ============================ fused kernel ==================================
__global__ __launch_bounds__(256, 3)
void fused_kernel(const float* __restrict__ XQ, const float* __restrict__ XK,
                  const float* __restrict__ XV, const float* __restrict__ W1,
                  const float* __restrict__ b1, const float* __restrict__ gam,
                  const float* __restrict__ bet, float* __restrict__ out)
{
    extern __shared__ float sm[];
    const int bid = blockIdx.x;

    if (bid < NBH) {
        // scan role: 128 threads; the rest exit (post-Volta syncthreads OK)
        if (threadIdx.x >= 128) return;
        scan_role(sm, bid, XK, XV, W1, b1, gam, bet);
        return;
    }
    const int cid = bid - NBH;
    const int c   = cid >> 6;      // chunk-major: early waves need early chunks
    const int bh  = cid & 63;
    chunk_role(sm, c, bh, XQ, XK, XV, gam, bet, out);
}

extern "C" void kernel_launch(void* const* d_in, const int* in_sizes, int n_in,
                              void* d_out, int out_size) {
    const float* XQ  = (const float*)d_in[0];
    const float* XK  = (const float*)d_in[1];
    const float* XV  = (const float*)d_in[2];
    const float* W1  = (const float*)d_in[3];
    const float* b1  = (const float*)d_in[4];
    const float* gam = (const float*)d_in[5];
    const float* bet = (const float*)d_in[6];
    float* out = (float*)d_out;

    const int smem = SMF * (int)sizeof(float);       // ~56 KB
    static int configured = 0;
    if (!configured) {
        cudaFuncSetAttribute(fused_kernel, cudaFuncAttributeMaxDynamicSharedMemorySize, smem);
        configured = 1;
    }
    reset_kernel<<<1, 64>>>();
    fused_kernel<<<NBH + NBH * NCHUNK, 256, smem>>>(XQ, XK, XV, W1, b1, gam, bet, out);
}